// round 7
// baseline (speedup 1.0000x reference)
#include <cuda_runtime.h>
#include <cstdint>

// LIF neuron: x is (N*T, F), row b = n*T + t, T=4, N=64, F=65536.
// Per (n,f): v=0; 4x { v = v*0.5 + x_t; s=(v>=1); v-=s; } out=s.
//
// R7: bulk-async (TMA-path) streaming. Each CTA handles one (n, column-tile):
// 4 x 4KB cp.async.bulk loads (one per timestep row) -> smem, compute the
// recurrence from smem, 4 x 4KB bulk stores back. DRAM sees contiguous
// multi-KB bursts instead of interleaved 128B sectors -> better row-buffer /
// R/W-turnaround efficiency (the binder per R1-R6: DRAM 59%, SM side idle).

#define T_STEPS 4
#define DECAY 0.5f
#define VTH 1.0f

#define F_TOTAL 65536
#define TILE_F 1024                      // floats per row-tile
#define TILE_BYTES (TILE_F * 4)          // 4096 B per bulk op
#define TILES_PER_N (F_TOTAL / TILE_F)   // 64
#define SMEM_BYTES (2 * T_STEPS * TILE_BYTES)  // 32 KB (in + out)

__global__ void __launch_bounds__(256) lif_tma_kernel(const float* __restrict__ x,
                                                      float* __restrict__ out)
{
    extern __shared__ float4 smem4[];    // in: [0,1024) float4, out: [1024,2048)
    __shared__ uint64_t mbar;

    unsigned n = blockIdx.x >> 6;        // / TILES_PER_N
    unsigned c = blockIdx.x & 63;        // % TILES_PER_N

    const float* src_base = x   + (size_t)n * (T_STEPS * F_TOTAL) + c * TILE_F;
    float*       dst_base = out + (size_t)n * (T_STEPS * F_TOTAL) + c * TILE_F;

    uint32_t smem_in   = (uint32_t)__cvta_generic_to_shared(smem4);
    uint32_t smem_out  = smem_in + T_STEPS * TILE_BYTES;
    uint32_t mbar_addr = (uint32_t)__cvta_generic_to_shared(&mbar);

    if (threadIdx.x == 0) {
        asm volatile("mbarrier.init.shared.b64 [%0], %1;"
                     :: "r"(mbar_addr), "r"(1u) : "memory");
    }
    __syncthreads();

    if (threadIdx.x == 0) {
        asm volatile("mbarrier.arrive.expect_tx.shared.b64 _, [%0], %1;"
                     :: "r"(mbar_addr), "r"((unsigned)(T_STEPS * TILE_BYTES))
                     : "memory");
#pragma unroll
        for (int t = 0; t < T_STEPS; t++) {
            asm volatile(
                "cp.async.bulk.shared::cta.global.mbarrier::complete_tx::bytes "
                "[%0], [%1], %2, [%3];"
                :: "r"(smem_in + t * TILE_BYTES),
                   "l"(src_base + t * F_TOTAL),
                   "r"((unsigned)TILE_BYTES),
                   "r"(mbar_addr)
                : "memory");
        }
    }

    // Wait for all 4 row-tiles (parity 0; barrier used exactly once per CTA).
    asm volatile(
        "{\n\t"
        ".reg .pred P;\n"
        "WAIT_%=:\n\t"
        "mbarrier.try_wait.parity.acquire.cta.shared::cta.b64 P, [%0], 0;\n\t"
        "@!P bra WAIT_%=;\n\t"
        "}"
        :: "r"(mbar_addr) : "memory");

    // Compute: thread i owns float4 column i (TILE_F/4 == 256 == blockDim).
    {
        int i = threadIdx.x;
        float4 v = make_float4(0.f, 0.f, 0.f, 0.f);
#pragma unroll
        for (int t = 0; t < T_STEPS; t++) {
            float4 xt = smem4[t * 256 + i];
            float4 s;
            v.x = v.x * DECAY + xt.x; s.x = (v.x >= VTH) ? 1.f : 0.f; v.x -= s.x * VTH;
            v.y = v.y * DECAY + xt.y; s.y = (v.y >= VTH) ? 1.f : 0.f; v.y -= s.y * VTH;
            v.z = v.z * DECAY + xt.z; s.z = (v.z >= VTH) ? 1.f : 0.f; v.z -= s.z * VTH;
            v.w = v.w * DECAY + xt.w; s.w = (v.w >= VTH) ? 1.f : 0.f; v.w -= s.w * VTH;
            smem4[(T_STEPS + t) * 256 + i] = s;
        }
    }
    __syncthreads();

    if (threadIdx.x == 0) {
        asm volatile("fence.proxy.async;" ::: "memory");
#pragma unroll
        for (int t = 0; t < T_STEPS; t++) {
            asm volatile(
                "cp.async.bulk.global.shared::cta.bulk_group [%0], [%1], %2;"
                :: "l"(dst_base + t * F_TOTAL),
                   "r"(smem_out + t * TILE_BYTES),
                   "r"((unsigned)TILE_BYTES)
                : "memory");
        }
        asm volatile("cp.async.bulk.commit_group;" ::: "memory");
        // Keep CTA alive until stores have read smem.
        asm volatile("cp.async.bulk.wait_group 0;" ::: "memory");
    }
}

extern "C" void kernel_launch(void* const* d_in, const int* in_sizes, int n_in,
                              void* d_out, int out_size)
{
    const float* x = (const float*)d_in[0];
    float* out = (float*)d_out;

    cudaFuncSetAttribute(lif_tma_kernel,
                         cudaFuncAttributeMaxDynamicSharedMemorySize, SMEM_BYTES);

    const int N = 64;                           // 256 rows / T=4
    int blocks = N * TILES_PER_N;               // 4096 CTAs
    lif_tma_kernel<<<blocks, 256, SMEM_BYTES>>>(x, out);
}

// round 8
// speedup vs baseline: 1.0894x; 1.0894x over previous
#include <cuda_runtime.h>

// LIF neuron: x is (N*T, F), row b = n*T + t, T=4, N=64, F=65536.
// Per (n,f): v=0; 4x { v = v*0.5 + x_t; s=(v>=1); v-=s; } out=s.
//
// R8: single-wave launch. 1024 CTAs x 256 thr (~7 CTAs/SM, all co-resident)
// each thread processes exactly 4 grid-strided float4 columns with the R3
// body (streaming ldcs/stcs). Eliminates the 3.46-wave structure of the 4096-
// CTA launch (wave transitions + tail), which is the remaining non-memory
// cost: SM side idle (issue 12%), DRAM-path already at device mixed-stream cap.

#define T_STEPS 4
#define DECAY 0.5f
#define VTH 1.0f

#define FVEC 16384              // F/4
#define NBLOCKS 1024
#define NTHREADS 256
#define STRIDE (NBLOCKS * NTHREADS)     // 262,144
#define TOTAL (64 * FVEC)               // 1,048,576 f4 elements
#define ITERS (TOTAL / STRIDE)          // 4

__global__ void __launch_bounds__(NTHREADS) lif_kernel(const float4* __restrict__ x,
                                                       float4* __restrict__ out)
{
    unsigned e = blockIdx.x * NTHREADS + threadIdx.x;

#pragma unroll
    for (int k = 0; k < ITERS; k++, e += STRIDE) {
        unsigned n  = e >> 14;          // / FVEC
        unsigned f4 = e & (FVEC - 1);   // % FVEC
        unsigned base = n * (T_STEPS * FVEC) + f4;

        // Front-batch 4 streaming loads (MLP=4 per iteration).
        float4 x0 = __ldcs(&x[base]);
        float4 x1 = __ldcs(&x[base + FVEC]);
        float4 x2 = __ldcs(&x[base + 2 * FVEC]);
        float4 x3 = __ldcs(&x[base + 3 * FVEC]);

        float4 v = make_float4(0.f, 0.f, 0.f, 0.f);
        float4 s0, s1, s2, s3;

#define STEP1(vc, xt, st)                                                  \
        (vc) = (vc) * DECAY + (xt); (st) = ((vc) >= VTH) ? 1.f : 0.f; (vc) -= (st) * VTH;
#define STEP4(xt, st)            \
        STEP1(v.x, (xt).x, (st).x)   \
        STEP1(v.y, (xt).y, (st).y)   \
        STEP1(v.z, (xt).z, (st).z)   \
        STEP1(v.w, (xt).w, (st).w)

        STEP4(x0, s0)
        STEP4(x1, s1)
        STEP4(x2, s2)
        STEP4(x3, s3)
#undef STEP4
#undef STEP1

        __stcs(&out[base],            s0);
        __stcs(&out[base + FVEC],     s1);
        __stcs(&out[base + 2 * FVEC], s2);
        __stcs(&out[base + 3 * FVEC], s3);
    }
}

extern "C" void kernel_launch(void* const* d_in, const int* in_sizes, int n_in,
                              void* d_out, int out_size)
{
    const float* x = (const float*)d_in[0];
    float* out = (float*)d_out;

    lif_kernel<<<NBLOCKS, NTHREADS>>>((const float4*)x, (float4*)out);
}

// round 9
// speedup vs baseline: 1.1015x; 1.0111x over previous
#include <cuda_runtime.h>

// LIF neuron: x is (N*T, F), row b = n*T + t, T=4, N=64, F=65536.
// Per (n,f): v=0; 4x { v = v*0.5 + x_t; s=(v>=1); v-=s; } out=s.
//
// R9: combine best-measured ingredients. R2 shape (2048 CTAs, 2 float4/thread,
// 8 front-batched loads) + R3 streaming hints (ldcs/stcs; no reuse, working
// set > L2) + 32-bit shift/mask indexing. We are at the ~17.6us LTS-cap floor
// (134MB / 7.6TB/s); this hunts the last fraction of sector efficiency.

#define T_STEPS 4
#define DECAY 0.5f
#define VTH 1.0f

#define FVEC 16384          // F/4
#define F4_PER_BLOCK 512    // 256 threads x 2 float4
#define BLOCKS_PER_N 32     // FVEC / F4_PER_BLOCK

__global__ void __launch_bounds__(256) lif_kernel(const float4* __restrict__ x,
                                                  float4* __restrict__ out)
{
    unsigned n = blockIdx.x >> 5;           // / BLOCKS_PER_N
    unsigned c = blockIdx.x & 31;           // % BLOCKS_PER_N

    unsigned f4a = c * F4_PER_BLOCK + threadIdx.x;   // first column
    unsigned a = n * (T_STEPS * FVEC) + f4a;         // fits in u32
    unsigned b = a + 256u;                           // second column

    // Front-batch all 8 streaming loads (MLP_p1 = 8).
    float4 xa0 = __ldcs(&x[a]);
    float4 xa1 = __ldcs(&x[a + FVEC]);
    float4 xa2 = __ldcs(&x[a + 2 * FVEC]);
    float4 xa3 = __ldcs(&x[a + 3 * FVEC]);
    float4 xb0 = __ldcs(&x[b]);
    float4 xb1 = __ldcs(&x[b + FVEC]);
    float4 xb2 = __ldcs(&x[b + 2 * FVEC]);
    float4 xb3 = __ldcs(&x[b + 3 * FVEC]);

    float4 va = make_float4(0.f, 0.f, 0.f, 0.f);
    float4 vb = make_float4(0.f, 0.f, 0.f, 0.f);
    float4 sa0, sa1, sa2, sa3, sb0, sb1, sb2, sb3;

#define STEP1(v, xt, st)                                                  \
    (v) = (v) * DECAY + (xt); (st) = ((v) >= VTH) ? 1.f : 0.f; (v) -= (st) * VTH;
#define STEP4(v, xt, st)            \
    STEP1(v.x, (xt).x, (st).x)      \
    STEP1(v.y, (xt).y, (st).y)      \
    STEP1(v.z, (xt).z, (st).z)      \
    STEP1(v.w, (xt).w, (st).w)

    STEP4(va, xa0, sa0)
    STEP4(va, xa1, sa1)
    STEP4(va, xa2, sa2)
    STEP4(va, xa3, sa3)
    STEP4(vb, xb0, sb0)
    STEP4(vb, xb1, sb1)
    STEP4(vb, xb2, sb2)
    STEP4(vb, xb3, sb3)
#undef STEP4
#undef STEP1

    __stcs(&out[a],            sa0);
    __stcs(&out[b],            sb0);
    __stcs(&out[a + FVEC],     sa1);
    __stcs(&out[b + FVEC],     sb1);
    __stcs(&out[a + 2 * FVEC], sa2);
    __stcs(&out[b + 2 * FVEC], sb2);
    __stcs(&out[a + 3 * FVEC], sa3);
    __stcs(&out[b + 3 * FVEC], sb3);
}

extern "C" void kernel_launch(void* const* d_in, const int* in_sizes, int n_in,
                              void* d_out, int out_size)
{
    const float* x = (const float*)d_in[0];
    float* out = (float*)d_out;

    const int N = 64;                       // 256 rows / T=4
    int blocks = N * BLOCKS_PER_N;          // 2048 blocks x 256 threads

    lif_kernel<<<blocks, 256>>>((const float4*)x, (float4*)out);
}

// round 10
// speedup vs baseline: 1.1928x; 1.0828x over previous
#include <cuda_runtime.h>

// LIF neuron: x is (N*T, F), row b = n*T + t, T=4, N=64, F=65536.
// Per (n,f): v=0; 4x { v = v*0.5 + x_t; s=(v>=1); v-=s; } out=s.
//
// R10: exact R3 champion shape (4096 CTAs x 256, 1 float4 column/thread,
// streaming ldcs loads, 32-bit shift/mask indexing, 30 regs / occ 77%),
// with write-through stores (stwt). Writebacks become store-driven and
// smooth instead of eviction-driven bursts correlated with read misses;
// same DRAM bytes, better R/W interleaving at the memory controller.

#define T_STEPS 4
#define DECAY 0.5f
#define VTH 1.0f

#define FVEC 16384          // F/4
#define BLOCKS_PER_N 64     // FVEC / 256 threads

__global__ void __launch_bounds__(256) lif_kernel(const float4* __restrict__ x,
                                                  float4* __restrict__ out)
{
    // blockIdx.x = n * BLOCKS_PER_N + c ; power-of-two split, all 32-bit.
    unsigned n = blockIdx.x >> 6;              // / 64
    unsigned c = blockIdx.x & 63;              // % 64

    unsigned base = n * (T_STEPS * FVEC) + c * 256u + threadIdx.x;

    // Front-batch 4 streaming loads (evict-first: no intra-replay reuse).
    float4 x0 = __ldcs(&x[base]);
    float4 x1 = __ldcs(&x[base + FVEC]);
    float4 x2 = __ldcs(&x[base + 2 * FVEC]);
    float4 x3 = __ldcs(&x[base + 3 * FVEC]);

    float4 v = make_float4(0.f, 0.f, 0.f, 0.f);
    float4 s0, s1, s2, s3;

#define STEP1(vc, xt, st)                                                  \
    (vc) = (vc) * DECAY + (xt); (st) = ((vc) >= VTH) ? 1.f : 0.f; (vc) -= (st) * VTH;
#define STEP4(xt, st)            \
    STEP1(v.x, (xt).x, (st).x)   \
    STEP1(v.y, (xt).y, (st).y)   \
    STEP1(v.z, (xt).z, (st).z)   \
    STEP1(v.w, (xt).w, (st).w)

    STEP4(x0, s0)
    STEP4(x1, s1)
    STEP4(x2, s2)
    STEP4(x3, s3)
#undef STEP4
#undef STEP1

    // Write-through stores: smooth, store-driven DRAM write stream.
    __stwt(&out[base],            s0);
    __stwt(&out[base + FVEC],     s1);
    __stwt(&out[base + 2 * FVEC], s2);
    __stwt(&out[base + 3 * FVEC], s3);
}

extern "C" void kernel_launch(void* const* d_in, const int* in_sizes, int n_in,
                              void* d_out, int out_size)
{
    const float* x = (const float*)d_in[0];
    float* out = (float*)d_out;

    const int N = 64;                       // 256 rows / T=4
    int blocks = N * BLOCKS_PER_N;          // 4096 blocks x 256 threads

    lif_kernel<<<blocks, 256>>>((const float4*)x, (float4*)out);
}

// round 11
// speedup vs baseline: 1.2092x; 1.0137x over previous
#include <cuda_runtime.h>

// LIF neuron: x is (N*T, F), row b = n*T + t, T=4, N=64, F=65536.
// Per (n,f): v=0; 4x { v = v*0.5 + x_t; s=(v>=1); v-=s; } out=s.
//
// FINAL (== R3 champion, re-validated): this problem is bound by the LTS
// throughput cap (~6300 B/cyc, path-independent): 134MB compulsory L2 traffic
// / ~7.6 TB/s = ~17.6us kernel floor, confirmed across 10 structurally
// different variants (MLP depth, L2 pinning both directions, 256-bit ops,
// TMA bursts, single-wave, write-through — all neutral or worse).
// Config: 4096 CTAs x 256 thr, one float4 column per thread, front-batched
// evict-first loads, evict-first stores, 32-bit shift/mask indexing.

#define T_STEPS 4
#define DECAY 0.5f
#define VTH 1.0f

#define FVEC 16384          // F/4
#define BLOCKS_PER_N 64     // FVEC / 256 threads

__global__ void __launch_bounds__(256) lif_kernel(const float4* __restrict__ x,
                                                  float4* __restrict__ out)
{
    // blockIdx.x = n * BLOCKS_PER_N + c ; power-of-two split, all 32-bit.
    unsigned n = blockIdx.x >> 6;              // / 64
    unsigned c = blockIdx.x & 63;              // % 64

    unsigned base = n * (T_STEPS * FVEC) + c * 256u + threadIdx.x;

    // Front-batch 4 streaming loads (evict-first; no intra-kernel reuse).
    float4 x0 = __ldcs(&x[base]);
    float4 x1 = __ldcs(&x[base + FVEC]);
    float4 x2 = __ldcs(&x[base + 2 * FVEC]);
    float4 x3 = __ldcs(&x[base + 3 * FVEC]);

    float4 v = make_float4(0.f, 0.f, 0.f, 0.f);
    float4 s0, s1, s2, s3;

#define STEP1(vc, xt, st)                                                  \
    (vc) = (vc) * DECAY + (xt); (st) = ((vc) >= VTH) ? 1.f : 0.f; (vc) -= (st) * VTH;
#define STEP4(xt, st)            \
    STEP1(v.x, (xt).x, (st).x)   \
    STEP1(v.y, (xt).y, (st).y)   \
    STEP1(v.z, (xt).z, (st).z)   \
    STEP1(v.w, (xt).w, (st).w)

    STEP4(x0, s0)
    STEP4(x1, s1)
    STEP4(x2, s2)
    STEP4(x3, s3)
#undef STEP4
#undef STEP1

    __stcs(&out[base],            s0);
    __stcs(&out[base + FVEC],     s1);
    __stcs(&out[base + 2 * FVEC], s2);
    __stcs(&out[base + 3 * FVEC], s3);
}

extern "C" void kernel_launch(void* const* d_in, const int* in_sizes, int n_in,
                              void* d_out, int out_size)
{
    const float* x = (const float*)d_in[0];
    float* out = (float*)d_out;

    const int N = 64;                       // 256 rows / T=4
    int blocks = N * BLOCKS_PER_N;          // 4096 blocks x 256 threads

    lif_kernel<<<blocks, 256>>>((const float4*)x, (float4*)out);
}